// round 7
// baseline (speedup 1.0000x reference)
#include <cuda_runtime.h>
#include <cuda_fp16.h>

#define N_NODES 100000
#define N_EDGES 1600000
#define D 48
#define D4 (D / 4)

#define T 256
#define GEMM_BLOCKS 148
#define NODE_CHUNK ((N_NODES + GEMM_BLOCKS - 1) / GEMM_BLOCKS)   // 676
#define AGG_U4 (N_NODES * D / 8)                                  // 600000 per buffer
#define ZERO_BLOCKS ((2 * AGG_U4 + T - 1) / T)                    // zero both buffers

// Device scratch (no allocations allowed):
__device__ __half g_xw[N_NODES * D];     // x @ w in fp16 (9.6 MB)
__device__ __half g_agg0[N_NODES * D];   // fp16 accumulator, even edges (9.6 MB)
__device__ __half g_agg1[N_NODES * D];   // fp16 accumulator, odd edges  (9.6 MB)

// ---------------------------------------------------------------------------
// 2-node GEMM body: computes xw rows for nodes n0 and (optionally) n1.
// ---------------------------------------------------------------------------
__device__ __forceinline__ void gemm_pair(const float* __restrict__ x,
                                          const float* ws,
                                          int n0, int n1, bool has1) {
    float4 xa[D4], xb[D4];
    const float4* xp0 = (const float4*)(x + (size_t)n0 * D);
    const float4* xp1 = (const float4*)(x + (size_t)n1 * D);
#pragma unroll
    for (int k4 = 0; k4 < D4; k4++) {
        xa[k4] = xp0[k4];
        xb[k4] = has1 ? xp1[k4] : make_float4(0.f, 0.f, 0.f, 0.f);
    }

    __half* hp0 = g_xw + (size_t)n0 * D;
    __half* hp1 = g_xw + (size_t)n1 * D;

#pragma unroll
    for (int j4 = 0; j4 < D4; j4++) {
        float a0 = 0.f, a1 = 0.f, a2 = 0.f, a3 = 0.f;
        float b0 = 0.f, b1 = 0.f, b2 = 0.f, b3 = 0.f;
#pragma unroll
        for (int k4 = 0; k4 < D4; k4++) {
            float4 va = xa[k4];
            float4 vb = xb[k4];
#pragma unroll
            for (int t = 0; t < 4; t++) {
                int k = k4 * 4 + t;
                float xav = (t == 0) ? va.x : (t == 1) ? va.y : (t == 2) ? va.z : va.w;
                float xbv = (t == 0) ? vb.x : (t == 1) ? vb.y : (t == 2) ? vb.z : vb.w;
                float4 wr = *(const float4*)(ws + k * D + j4 * 4);
                a0 = fmaf(xav, wr.x, a0);
                a1 = fmaf(xav, wr.y, a1);
                a2 = fmaf(xav, wr.z, a2);
                a3 = fmaf(xav, wr.w, a3);
                b0 = fmaf(xbv, wr.x, b0);
                b1 = fmaf(xbv, wr.y, b1);
                b2 = fmaf(xbv, wr.z, b2);
                b3 = fmaf(xbv, wr.w, b3);
            }
        }
        __half2 ha[2], hb[2];
        ha[0] = __floats2half2_rn(a0, a1);
        ha[1] = __floats2half2_rn(a2, a3);
        hb[0] = __floats2half2_rn(b0, b1);
        hb[1] = __floats2half2_rn(b2, b3);
        *(uint2*)(hp0 + j4 * 4) = *(const uint2*)ha;
        if (has1) *(uint2*)(hp1 + j4 * 4) = *(const uint2*)hb;
    }
}

// ---------------------------------------------------------------------------
// Kernel 1 (fused): blocks [0,148) = GEMM over an even 676-node chunk each
// (one per SM — no tail imbalance); remaining blocks zero both agg buffers.
// ---------------------------------------------------------------------------
__global__ void __launch_bounds__(256, 2)
gemm_zero_kernel(const float* __restrict__ x, const float* __restrict__ w) {
    if (blockIdx.x >= GEMM_BLOCKS) {
        int i = (blockIdx.x - GEMM_BLOCKS) * blockDim.x + threadIdx.x;
        if (i < AGG_U4)          ((uint4*)g_agg0)[i] = make_uint4(0u, 0u, 0u, 0u);
        else if (i < 2 * AGG_U4) ((uint4*)g_agg1)[i - AGG_U4] = make_uint4(0u, 0u, 0u, 0u);
        return;
    }

    __shared__ float ws[D * D];
    for (int i = threadIdx.x; i < D * D; i += blockDim.x) ws[i] = w[i];
    __syncthreads();

    int start = blockIdx.x * NODE_CHUNK;
    int end   = min(start + NODE_CHUNK, N_NODES);

    int n = start + threadIdx.x;
    while (n + 256 < end) {                  // full pairs
        gemm_pair(x, ws, n, n + 256, true);
        n += 512;
    }
    if (n < end)                             // ragged tail: single node
        gemm_pair(x, ws, n, n, false);
}

// ---------------------------------------------------------------------------
// Kernel 2: COO scatter, fp16 gather + fp16x2 vector RED.
// 6 lanes per edge; parity of the edge selects the accumulator buffer
// (two shorter fp16 accumulation chains -> ~sqrt(2) lower rounding error).
// ---------------------------------------------------------------------------
__global__ void scatter_kernel(const int* __restrict__ src,
                               const int* __restrict__ dst,
                               const float* __restrict__ vals) {
    int tid = blockIdx.x * blockDim.x + threadIdx.x;
    if (tid >= N_EDGES * 6) return;
    int e = tid / 6;
    int c = tid - e * 6;

    int s = __ldg(src + e);
    int d = __ldg(dst + e);
    float a = __ldg(vals + e);

    float4 raw = *(const float4*)(g_xw + (size_t)s * D + c * 8);
    const __half2* h = (const __half2*)&raw;
    unsigned r[4];
#pragma unroll
    for (int t = 0; t < 4; t++) {
        float2 f = __half22float2(h[t]);
        __half2 o = __floats2half2_rn(a * f.x, a * f.y);
        r[t] = *(const unsigned*)&o;
    }

    __half* base = (e & 1) ? g_agg1 : g_agg0;
    __half* p = base + (size_t)d * D + c * 8;
    asm volatile("red.global.add.noftz.v4.f16x2 [%0], {%1, %2, %3, %4};"
                 :: "l"(p), "r"(r[0]), "r"(r[1]), "r"(r[2]), "r"(r[3])
                 : "memory");
}

// ---------------------------------------------------------------------------
// Kernel 3: out = relu(agg0 + agg1 + b), fp32 combine.
// ---------------------------------------------------------------------------
__global__ void finalize_kernel(const float* __restrict__ b,
                                float* __restrict__ out) {
    int i = blockIdx.x * blockDim.x + threadIdx.x;
    if (i >= AGG_U4) return;
    int c = i % 6;

    uint4 r0 = *((const uint4*)g_agg0 + i);
    uint4 r1 = *((const uint4*)g_agg1 + i);
    const __half2* h0 = (const __half2*)&r0;
    const __half2* h1 = (const __half2*)&r1;

    float bb[8];
    *(float4*)(bb)     = *(const float4*)(b + c * 8);
    *(float4*)(bb + 4) = *(const float4*)(b + c * 8 + 4);

    float4 o0, o1;
#pragma unroll
    for (int t = 0; t < 4; t++) {
        float2 f0 = __half22float2(h0[t]);
        float2 f1 = __half22float2(h1[t]);
        float vx = f0.x + f1.x + bb[2 * t];
        float vy = f0.y + f1.y + bb[2 * t + 1];
        float* o = (t < 2) ? (float*)&o0 : (float*)&o1;
        o[(t & 1) * 2 + 0] = fmaxf(vx, 0.f);
        o[(t & 1) * 2 + 1] = fmaxf(vy, 0.f);
    }

    float4* op = (float4*)(out + (size_t)i * 8);
    op[0] = o0;
    op[1] = o1;
}

// ---------------------------------------------------------------------------
extern "C" void kernel_launch(void* const* d_in, const int* in_sizes, int n_in,
                              void* d_out, int out_size) {
    const float* x        = (const float*)d_in[0];
    const float* w        = (const float*)d_in[1];
    const float* b        = (const float*)d_in[2];
    const int*   edge_src = (const int*)d_in[3];
    const int*   edge_dst = (const int*)d_in[4];
    const float* adj_vals = (const float*)d_in[5];
    float* out = (float*)d_out;

    // 1) fused GEMM (148 balanced blocks) + zero both agg buffers
    gemm_zero_kernel<<<GEMM_BLOCKS + ZERO_BLOCKS, T>>>(x, w);
    // 2) scatter-add over edges (fp16 gather, fp16x2 vector RED, parity split)
    {
        int total = N_EDGES * 6;
        scatter_kernel<<<(total + T - 1) / T, T>>>(edge_src, edge_dst, adj_vals);
    }
    // 3) out = relu(agg0 + agg1 + b)
    finalize_kernel<<<(AGG_U4 + T - 1) / T, T>>>(b, out);
}

// round 8
// speedup vs baseline: 1.3175x; 1.3175x over previous
#include <cuda_runtime.h>
#include <cuda_fp16.h>

#define N_NODES 100000
#define N_EDGES 1600000
#define D 48
#define D4 (D / 4)

#define T 256
#define ROW_U4 (D / 8)                                   // 6 uint4 per fp16 row
#define XH_U4 (N_NODES * ROW_U4)                         // 600000
#define CZ_TOTAL (3 * XH_U4)                             // convert + zero two aggs
#define CZ_BLOCKS ((CZ_TOTAL + T - 1) / T)
#define GF_NODES_PER_BLK (2 * T)                         // 512
#define GF_BLOCKS ((N_NODES + GF_NODES_PER_BLK - 1) / GF_NODES_PER_BLK)  // 196

// Device scratch (no allocations allowed):
__device__ __half g_xh[N_NODES * D];     // x in fp16 (9.6 MB)
__device__ __half g_agg0[N_NODES * D];   // fp16 accumulator, even edges
__device__ __half g_agg1[N_NODES * D];   // fp16 accumulator, odd edges

// ---------------------------------------------------------------------------
// Kernel 1: convert x -> fp16 AND zero both agg buffers (all streaming).
// ---------------------------------------------------------------------------
__global__ void convert_zero_kernel(const float* __restrict__ x) {
    int i = blockIdx.x * blockDim.x + threadIdx.x;
    if (i >= CZ_TOTAL) return;
    if (i < XH_U4) {
        const float4* xp = (const float4*)x + (size_t)i * 2;
        float4 v0 = xp[0];
        float4 v1 = xp[1];
        __half2 h[4];
        h[0] = __floats2half2_rn(v0.x, v0.y);
        h[1] = __floats2half2_rn(v0.z, v0.w);
        h[2] = __floats2half2_rn(v1.x, v1.y);
        h[3] = __floats2half2_rn(v1.z, v1.w);
        ((uint4*)g_xh)[i] = *(const uint4*)h;
    } else if (i < 2 * XH_U4) {
        ((uint4*)g_agg0)[i - XH_U4] = make_uint4(0u, 0u, 0u, 0u);
    } else {
        ((uint4*)g_agg1)[i - 2 * XH_U4] = make_uint4(0u, 0u, 0u, 0u);
    }
}

// ---------------------------------------------------------------------------
// Kernel 2: COO scatter of RAW x rows: agg[dst] += a_e * xh[src].
// 6 lanes per edge, one red.v4.f16x2 (16 B) each -> contiguous 96 B per edge.
// Edge parity selects the accumulator buffer (shorter fp16 chains).
// ---------------------------------------------------------------------------
__global__ void scatter_kernel(const int* __restrict__ src,
                               const int* __restrict__ dst,
                               const float* __restrict__ vals) {
    int tid = blockIdx.x * blockDim.x + threadIdx.x;
    if (tid >= N_EDGES * 6) return;
    int e = tid / 6;
    int c = tid - e * 6;

    int s = __ldg(src + e);
    int d = __ldg(dst + e);
    float a = __ldg(vals + e);

    float4 raw = *(const float4*)(g_xh + (size_t)s * D + c * 8);
    const __half2* h = (const __half2*)&raw;
    unsigned r[4];
#pragma unroll
    for (int t = 0; t < 4; t++) {
        float2 f = __half22float2(h[t]);
        __half2 o = __floats2half2_rn(a * f.x, a * f.y);
        r[t] = *(const unsigned*)&o;
    }

    __half* base = (e & 1) ? g_agg1 : g_agg0;
    __half* p = base + (size_t)d * D + c * 8;
    asm volatile("red.global.add.noftz.v4.f16x2 [%0], {%1, %2, %3, %4};"
                 :: "l"(p), "r"(r[0]), "r"(r[1]), "r"(r[2]), "r"(r[3])
                 : "memory");
}

// ---------------------------------------------------------------------------
// Kernel 3: out[n] = relu( (agg0[n] + agg1[n]) @ w + b ).
// Two nodes per thread (R6-proven shape); w + b in shared memory.
// ---------------------------------------------------------------------------
__global__ void __launch_bounds__(256, 2)
gemm_finalize_kernel(const float* __restrict__ w,
                     const float* __restrict__ b,
                     float* __restrict__ out) {
    __shared__ float ws[D * D];
    __shared__ float bs[D];
    for (int i = threadIdx.x; i < D * D; i += blockDim.x) ws[i] = w[i];
    if (threadIdx.x < D) bs[threadIdx.x] = b[threadIdx.x];
    __syncthreads();

    int base = blockIdx.x * GF_NODES_PER_BLK + threadIdx.x;
    int n0 = base;
    int n1 = base + blockDim.x;
    bool has0 = (n0 < N_NODES);
    bool has1 = (n1 < N_NODES);
    if (!has0) return;

    // load agg rows (fp16 x2 buffers), combine to fp32
    float xa[D], xb[D];
    {
        const uint4* p00 = (const uint4*)(g_agg0 + (size_t)n0 * D);
        const uint4* p01 = (const uint4*)(g_agg1 + (size_t)n0 * D);
        const uint4* p10 = (const uint4*)(g_agg0 + (size_t)n1 * D);
        const uint4* p11 = (const uint4*)(g_agg1 + (size_t)n1 * D);
#pragma unroll
        for (int q = 0; q < ROW_U4; q++) {
            uint4 r0 = p00[q];
            uint4 r1 = p01[q];
            const __half2* h0 = (const __half2*)&r0;
            const __half2* h1 = (const __half2*)&r1;
#pragma unroll
            for (int t = 0; t < 4; t++) {
                float2 f0 = __half22float2(h0[t]);
                float2 f1 = __half22float2(h1[t]);
                xa[q * 8 + 2 * t]     = f0.x + f1.x;
                xa[q * 8 + 2 * t + 1] = f0.y + f1.y;
            }
            uint4 s0 = has1 ? p10[q] : make_uint4(0u, 0u, 0u, 0u);
            uint4 s1 = has1 ? p11[q] : make_uint4(0u, 0u, 0u, 0u);
            const __half2* g0 = (const __half2*)&s0;
            const __half2* g1 = (const __half2*)&s1;
#pragma unroll
            for (int t = 0; t < 4; t++) {
                float2 f0 = __half22float2(g0[t]);
                float2 f1 = __half22float2(g1[t]);
                xb[q * 8 + 2 * t]     = f0.x + f1.x;
                xb[q * 8 + 2 * t + 1] = f0.y + f1.y;
            }
        }
    }

    float4* op0 = (float4*)(out + (size_t)n0 * D);
    float4* op1 = (float4*)(out + (size_t)n1 * D);

#pragma unroll
    for (int j4 = 0; j4 < D4; j4++) {
        float a0 = 0.f, a1 = 0.f, a2 = 0.f, a3 = 0.f;
        float b0 = 0.f, b1 = 0.f, b2 = 0.f, b3 = 0.f;
#pragma unroll
        for (int k = 0; k < D; k++) {
            float4 wr = *(const float4*)(ws + k * D + j4 * 4);
            float xav = xa[k];
            float xbv = xb[k];
            a0 = fmaf(xav, wr.x, a0);
            a1 = fmaf(xav, wr.y, a1);
            a2 = fmaf(xav, wr.z, a2);
            a3 = fmaf(xav, wr.w, a3);
            b0 = fmaf(xbv, wr.x, b0);
            b1 = fmaf(xbv, wr.y, b1);
            b2 = fmaf(xbv, wr.z, b2);
            b3 = fmaf(xbv, wr.w, b3);
        }
        float4 bb = *(const float4*)(bs + j4 * 4);
        float4 oa, ob;
        oa.x = fmaxf(a0 + bb.x, 0.f);
        oa.y = fmaxf(a1 + bb.y, 0.f);
        oa.z = fmaxf(a2 + bb.z, 0.f);
        oa.w = fmaxf(a3 + bb.w, 0.f);
        ob.x = fmaxf(b0 + bb.x, 0.f);
        ob.y = fmaxf(b1 + bb.y, 0.f);
        ob.z = fmaxf(b2 + bb.z, 0.f);
        ob.w = fmaxf(b3 + bb.w, 0.f);
        op0[j4] = oa;
        if (has1) op1[j4] = ob;
    }
}

// ---------------------------------------------------------------------------
extern "C" void kernel_launch(void* const* d_in, const int* in_sizes, int n_in,
                              void* d_out, int out_size) {
    const float* x        = (const float*)d_in[0];
    const float* w        = (const float*)d_in[1];
    const float* b        = (const float*)d_in[2];
    const int*   edge_src = (const int*)d_in[3];
    const int*   edge_dst = (const int*)d_in[4];
    const float* adj_vals = (const float*)d_in[5];
    float* out = (float*)d_out;

    // 1) convert x to fp16 + zero both agg buffers (streaming)
    convert_zero_kernel<<<CZ_BLOCKS, T>>>(x);
    // 2) scatter raw x rows: agg[dst] += a_e * xh[src]
    {
        int total = N_EDGES * 6;
        scatter_kernel<<<(total + T - 1) / T, T>>>(edge_src, edge_dst, adj_vals);
    }
    // 3) out = relu((agg0 + agg1) @ w + b)   — GEMM fused into finalize
    gemm_finalize_kernel<<<GF_BLOCKS, T>>>(w, b, out);
}